// round 15
// baseline (speedup 1.0000x reference)
#include <cuda_runtime.h>
#include <cuda_fp16.h>
#include <math_constants.h>
#include <mma.h>

using namespace nvcuda;

#define Nn 50000
#define Ee 800000
#define DIN 128
#define HID 32
#define HEADS 8
#define F1 (HEADS*HID)   // 256
#define NPAD 50048       // Nn rounded up to 128 (WMMA M-tile)
#define SB 49            // scan blocks = ceil(Nn/1024)

// ---------------- scratch (static device globals; no allocation) ----------------
// g_deg relies on zero-init for the first call; re-zeroed (zero_deg) each run.
__device__ __half g_hs1h[NPAD*F1];   // layer1 source features, fp16 [N,256]
__device__ __half g_aggh[NPAD*F1];   // layer1 output h, fp16 [N,256]
__device__ __half g_hs2h[NPAD*HID];  // layer2 source features, fp16 [N,32]
__device__ float g_as1[Nn*HEADS], g_ad1[Nn*HEADS];
__device__ float g_as2[Nn], g_ad2[Nn];
__device__ float g_Wsr1[HEADS*DIN], g_Wdr1[HEADS*DIN];   // [h][k] layout
__device__ float g_Wsr2[F1], g_Wdr2[F1];
__device__ int   g_deg[Nn];
__device__ int   g_rowptr[Nn + 1];
__device__ int   g_cursor[Nn];
__device__ int   g_esrc[Ee];
__device__ int   g_bsum[64];

__device__ __forceinline__ float leaky(float v) { return v > 0.f ? v : 0.2f * v; }

__device__ __forceinline__ uint2 pack4h(float4 v) {
    __half2 h0 = __floats2half2_rn(v.x, v.y);
    __half2 h1 = __floats2half2_rn(v.z, v.w);
    uint2 r;
    r.x = *reinterpret_cast<unsigned*>(&h0);
    r.y = *reinterpret_cast<unsigned*>(&h1);
    return r;
}

__device__ __forceinline__ bool detect_i64(const int* __restrict__ raw) {
    bool is_i64 = true;
    #pragma unroll
    for (int i = 0; i < 16; i++)
        if (raw[2*i + 1] != 0) is_i64 = false;
    return is_i64;
}

// ---------------- histogram of dst straight from raw edge buffer ----------------
__global__ void convert_hist(const int* __restrict__ raw) {
    bool is_i64 = detect_i64(raw);
    int e = blockIdx.x * blockDim.x + threadIdx.x;
    if (e >= Ee) return;
    int d = is_i64 ? raw[2*(Ee + e)] : raw[Ee + e];
    atomicAdd(&g_deg[d], 1);
}

// ---------------- per-1024-chunk scan ----------------
__global__ void scan_blocks() {
    __shared__ int sm[1024];
    int gid = blockIdx.x * 1024 + threadIdx.x;
    int v = (gid < Nn) ? g_deg[gid] : 0;
    sm[threadIdx.x] = v;
    __syncthreads();
    for (int off = 1; off < 1024; off <<= 1) {
        int t = (threadIdx.x >= off) ? sm[threadIdx.x - off] : 0;
        __syncthreads();
        sm[threadIdx.x] += t;
        __syncthreads();
    }
    if (gid < Nn) g_rowptr[gid] = sm[threadIdx.x] - v;
    if (threadIdx.x == 1023) g_bsum[blockIdx.x] = sm[1023];
}

__global__ void zero_deg() {
    int i = blockIdx.x * blockDim.x + threadIdx.x;
    if (i < Nn) g_deg[i] = 0;
}

// ---------------- add chunk offsets (scans the 49 block sums locally) ----------------
__global__ void scan_add() {
    __shared__ int pref[64];
    int t = threadIdx.x;
    if (t < 64) pref[t] = (t < SB) ? g_bsum[t] : 0;
    __syncthreads();
    if (t == 0) {
        int run = 0;
        #pragma unroll
        for (int i = 0; i < 64; i++) { int v = pref[i]; pref[i] = run; run += v; }
    }
    __syncthreads();
    int gid = blockIdx.x * blockDim.x + t;
    if (gid < Nn) {
        int r = g_rowptr[gid] + pref[gid >> 10];
        g_rowptr[gid] = r;
        g_cursor[gid] = r;
    }
    if (gid == 0) g_rowptr[Nn] = Ee;
}

// ---------------- CSR fill ----------------
__global__ void fill_kernel(const int* __restrict__ raw) {
    bool is_i64 = detect_i64(raw);
    int e = blockIdx.x * blockDim.x + threadIdx.x;
    if (e >= Ee) return;
    int s, d;
    if (is_i64) { s = raw[2*e]; d = raw[2*(Ee + e)]; }
    else        { s = raw[e];   d = raw[Ee + e]; }
    int pos = atomicAdd(&g_cursor[d], 1);
    g_esrc[pos] = s;
}

// ---------------- reduce attention weight vectors ----------------
__global__ void reduceW_kernel(const float* __restrict__ W1s, const float* __restrict__ W1d,
                               const float* __restrict__ a1s, const float* __restrict__ a1d,
                               const float* __restrict__ W2s, const float* __restrict__ W2d,
                               const float* __restrict__ a2s, const float* __restrict__ a2d) {
    int idx = blockIdx.x * blockDim.x + threadIdx.x;
    if (idx < HEADS*DIN) {
        int h = idx >> 7, k = idx & 127;
        float s = 0.f, d = 0.f;
        #pragma unroll
        for (int c = 0; c < HID; c++) {
            s += W1s[k*F1 + h*HID + c] * a1s[h*HID + c];
            d += W1d[k*F1 + h*HID + c] * a1d[h*HID + c];
        }
        g_Wsr1[h*DIN + k] = s;
        g_Wdr1[h*DIN + k] = d;
    } else if (idx < HEADS*DIN + F1) {
        int k = idx - HEADS*DIN;
        float s = 0.f, d = 0.f;
        #pragma unroll
        for (int c = 0; c < HID; c++) {
            s += W2s[k*HID + c] * a2s[c];
            d += W2d[k*HID + c] * a2d[c];
        }
        g_Wsr2[k] = s;
        g_Wdr2[k] = d;
    }
}

// ---------------- layer-1 GEMM via WMMA, K-tile 32, inline fp32->fp16 staging ----------------
__global__ void gemm1_wmma(const float* __restrict__ A, const float* __restrict__ B) {
    __shared__ __half As[128][40];
    __shared__ __half Bs[32][72];
    __shared__ float  Cst[8][16][20];
    int tid = threadIdx.x;
    int warp = tid >> 5, lane = tid & 31;
    int bm = blockIdx.y * 128, bn = blockIdx.x * 64;
    int wm = warp >> 1, wn = warp & 1;

    wmma::fragment<wmma::accumulator, 16, 16, 16, float> c[2][2];
    #pragma unroll
    for (int i = 0; i < 2; i++)
        #pragma unroll
        for (int j = 0; j < 2; j++)
            wmma::fill_fragment(c[i][j], 0.f);

    for (int k0 = 0; k0 < DIN; k0 += 32) {
        {
            int ar = tid >> 1, ac = (tid & 1) * 16;
            int gr = bm + ar;
            #pragma unroll
            for (int q = 0; q < 4; q++) {
                float4 v = make_float4(0.f, 0.f, 0.f, 0.f);
                if (gr < Nn) v = *reinterpret_cast<const float4*>(&A[gr*DIN + k0 + ac + q*4]);
                *reinterpret_cast<uint2*>(&As[ar][ac + q*4]) = pack4h(v);
            }
        }
        {
            int br = tid >> 3, bc = (tid & 7) * 8;
            #pragma unroll
            for (int q = 0; q < 2; q++) {
                float4 v = *reinterpret_cast<const float4*>(&B[(k0 + br)*F1 + bn + bc + q*4]);
                *reinterpret_cast<uint2*>(&Bs[br][bc + q*4]) = pack4h(v);
            }
        }
        __syncthreads();
        #pragma unroll
        for (int ks = 0; ks < 32; ks += 16) {
            wmma::fragment<wmma::matrix_a, 16, 16, 16, __half, wmma::row_major> a[2];
            wmma::fragment<wmma::matrix_b, 16, 16, 16, __half, wmma::row_major> b[2];
            #pragma unroll
            for (int i = 0; i < 2; i++)
                wmma::load_matrix_sync(a[i], &As[wm*32 + i*16][ks], 40);
            #pragma unroll
            for (int j = 0; j < 2; j++)
                wmma::load_matrix_sync(b[j], &Bs[ks][wn*32 + j*16], 72);
            #pragma unroll
            for (int i = 0; i < 2; i++)
                #pragma unroll
                for (int j = 0; j < 2; j++)
                    wmma::mma_sync(c[i][j], a[i], b[j], c[i][j]);
        }
        __syncthreads();
    }

    #pragma unroll
    for (int i = 0; i < 2; i++)
        #pragma unroll
        for (int j = 0; j < 2; j++) {
            wmma::store_matrix_sync(&Cst[warp][0][0], c[i][j], 20, wmma::mem_row_major);
            __syncwarp();
            int r = lane >> 1, cc = (lane & 1) * 8;
            int gr = bm + wm*32 + i*16 + r;
            if (gr < Nn) {
                float* p = &Cst[warp][r][cc];
                __half2 h[4];
                h[0] = __floats2half2_rn(p[0], p[1]);
                h[1] = __floats2half2_rn(p[2], p[3]);
                h[2] = __floats2half2_rn(p[4], p[5]);
                h[3] = __floats2half2_rn(p[6], p[7]);
                *reinterpret_cast<uint4*>(&g_hs1h[gr*F1 + bn + wn*32 + j*16 + cc]) =
                    *reinterpret_cast<uint4*>(h);
            }
            __syncwarp();
        }
}

// ---------------- layer-1 alphas: warp per node (fp32 x) ----------------
__global__ void alpha1_kernel(const float* __restrict__ x) {
    int warp = (blockIdx.x * blockDim.x + threadIdx.x) >> 5;
    if (warp >= Nn) return;
    int lane = threadIdx.x & 31;
    float xv0 = x[warp*DIN + lane];
    float xv1 = x[warp*DIN + 32 + lane];
    float xv2 = x[warp*DIN + 64 + lane];
    float xv3 = x[warp*DIN + 96 + lane];
    #pragma unroll
    for (int h = 0; h < HEADS; h++) {
        const float* ws = &g_Wsr1[h*DIN];
        const float* wd = &g_Wdr1[h*DIN];
        float s = xv0*ws[lane] + xv1*ws[32+lane] + xv2*ws[64+lane] + xv3*ws[96+lane];
        float d = xv0*wd[lane] + xv1*wd[32+lane] + xv2*wd[64+lane] + xv3*wd[96+lane];
        #pragma unroll
        for (int off = 16; off; off >>= 1) {
            s += __shfl_down_sync(0xffffffffu, s, off);
            d += __shfl_down_sync(0xffffffffu, d, off);
        }
        if (lane == 0) { g_as1[warp*HEADS + h] = s; g_ad1[warp*HEADS + h] = d; }
    }
}

// ---------------- layer-1 aggregate + inline softmax + fused layer-2 alphas ----------------
__device__ __forceinline__ void fma8h(float* acc, float w, uint4 u) {
    __half2 h0 = *reinterpret_cast<__half2*>(&u.x);
    __half2 h1 = *reinterpret_cast<__half2*>(&u.y);
    __half2 h2 = *reinterpret_cast<__half2*>(&u.z);
    __half2 h3 = *reinterpret_cast<__half2*>(&u.w);
    float2 f0 = __half22float2(h0);
    float2 f1 = __half22float2(h1);
    float2 f2 = __half22float2(h2);
    float2 f3 = __half22float2(h3);
    acc[0] += w*f0.x; acc[1] += w*f0.y;
    acc[2] += w*f1.x; acc[3] += w*f1.y;
    acc[4] += w*f2.x; acc[5] += w*f2.y;
    acc[6] += w*f3.x; acc[7] += w*f3.y;
}

__global__ void agg1_fused(const float* __restrict__ b1) {
    int node = (blockIdx.x * blockDim.x + threadIdx.x) >> 5;
    if (node >= Nn) return;
    int lane = threadIdx.x & 31;
    int wh = lane >> 2;
    float adv = g_ad1[node*HEADS + wh];
    int start = g_rowptr[node], end = g_rowptr[node + 1];

    float acc[8] = {};
    float wsum = 0.f;
    int j = start;
    for (; j + 4 <= end; j += 4) {
        int s0 = g_esrc[j], s1 = g_esrc[j+1], s2 = g_esrc[j+2], s3 = g_esrc[j+3];
        float w0 = __expf(leaky(g_as1[s0*HEADS + wh] + adv));
        float w1 = __expf(leaky(g_as1[s1*HEADS + wh] + adv));
        float w2 = __expf(leaky(g_as1[s2*HEADS + wh] + adv));
        float w3 = __expf(leaky(g_as1[s3*HEADS + wh] + adv));
        uint4 u0 = *reinterpret_cast<const uint4*>(&g_hs1h[s0*F1 + lane*8]);
        uint4 u1 = *reinterpret_cast<const uint4*>(&g_hs1h[s1*F1 + lane*8]);
        uint4 u2 = *reinterpret_cast<const uint4*>(&g_hs1h[s2*F1 + lane*8]);
        uint4 u3 = *reinterpret_cast<const uint4*>(&g_hs1h[s3*F1 + lane*8]);
        wsum += (w0 + w1) + (w2 + w3);
        fma8h(acc, w0, u0);
        fma8h(acc, w1, u1);
        fma8h(acc, w2, u2);
        fma8h(acc, w3, u3);
    }
    for (; j < end; j++) {
        int s0 = g_esrc[j];
        float w0 = __expf(leaky(g_as1[s0*HEADS + wh] + adv));
        uint4 u0 = *reinterpret_cast<const uint4*>(&g_hs1h[s0*F1 + lane*8]);
        wsum += w0;
        fma8h(acc, w0, u0);
    }
    float inv = 1.f / (wsum + 1e-16f);
    float4 bb0 = *reinterpret_cast<const float4*>(&b1[lane*8]);
    float4 bb1 = *reinterpret_cast<const float4*>(&b1[lane*8 + 4]);
    float o[8];
    o[0] = fmaxf(acc[0]*inv + bb0.x, 0.f); o[1] = fmaxf(acc[1]*inv + bb0.y, 0.f);
    o[2] = fmaxf(acc[2]*inv + bb0.z, 0.f); o[3] = fmaxf(acc[3]*inv + bb0.w, 0.f);
    o[4] = fmaxf(acc[4]*inv + bb1.x, 0.f); o[5] = fmaxf(acc[5]*inv + bb1.y, 0.f);
    o[6] = fmaxf(acc[6]*inv + bb1.z, 0.f); o[7] = fmaxf(acc[7]*inv + bb1.w, 0.f);
    uint2 p0 = pack4h(make_float4(o[0], o[1], o[2], o[3]));
    uint2 p1 = pack4h(make_float4(o[4], o[5], o[6], o[7]));
    *reinterpret_cast<uint4*>(&g_aggh[node*F1 + lane*8]) = make_uint4(p0.x, p0.y, p1.x, p1.y);

    // fused layer-2 alphas (fp32 h, pre-quantization)
    float4 ws0 = *reinterpret_cast<const float4*>(&g_Wsr2[lane*8]);
    float4 ws1 = *reinterpret_cast<const float4*>(&g_Wsr2[lane*8 + 4]);
    float4 wd0 = *reinterpret_cast<const float4*>(&g_Wdr2[lane*8]);
    float4 wd1 = *reinterpret_cast<const float4*>(&g_Wdr2[lane*8 + 4]);
    float s = o[0]*ws0.x + o[1]*ws0.y + o[2]*ws0.z + o[3]*ws0.w
            + o[4]*ws1.x + o[5]*ws1.y + o[6]*ws1.z + o[7]*ws1.w;
    float d = o[0]*wd0.x + o[1]*wd0.y + o[2]*wd0.z + o[3]*wd0.w
            + o[4]*wd1.x + o[5]*wd1.y + o[6]*wd1.z + o[7]*wd1.w;
    #pragma unroll
    for (int off = 16; off; off >>= 1) {
        s += __shfl_down_sync(0xffffffffu, s, off);
        d += __shfl_down_sync(0xffffffffu, d, off);
    }
    if (lane == 0) { g_as2[node] = s; g_ad2[node] = d; }
}

// ---------------- layer-2 GEMM via WMMA: hs2 = h[N,256] @ W2_src[256,32] ----------------
__global__ void gemm2_wmma(const float* __restrict__ W2s) {
    __shared__ __half Bs[256][40];
    __shared__ float  Cst[8][16][36];
    int tid = threadIdx.x;
    int warp = tid >> 5, lane = tid & 31;
    int bm = blockIdx.x * 128;

    {
        int row = tid;
        #pragma unroll
        for (int q = 0; q < 8; q++) {
            float4 v = *reinterpret_cast<const float4*>(&W2s[row*HID + q*4]);
            *reinterpret_cast<uint2*>(&Bs[row][q*4]) = pack4h(v);
        }
    }
    __syncthreads();

    wmma::fragment<wmma::accumulator, 16, 16, 16, float> c[2];
    wmma::fill_fragment(c[0], 0.f);
    wmma::fill_fragment(c[1], 0.f);

    const __half* arow = &g_aggh[(bm + warp*16)*F1];
    #pragma unroll
    for (int k0 = 0; k0 < F1; k0 += 16) {
        wmma::fragment<wmma::matrix_a, 16, 16, 16, __half, wmma::row_major> a;
        wmma::load_matrix_sync(a, arow + k0, F1);
        wmma::fragment<wmma::matrix_b, 16, 16, 16, __half, wmma::row_major> b0, b1;
        wmma::load_matrix_sync(b0, &Bs[k0][0], 40);
        wmma::load_matrix_sync(b1, &Bs[k0][16], 40);
        wmma::mma_sync(c[0], a, b0, c[0]);
        wmma::mma_sync(c[1], a, b1, c[1]);
    }

    wmma::store_matrix_sync(&Cst[warp][0][0],  c[0], 36, wmma::mem_row_major);
    wmma::store_matrix_sync(&Cst[warp][0][16], c[1], 36, wmma::mem_row_major);
    __syncwarp();
    int r = lane >> 1, cc = (lane & 1) * 16;
    int gr = bm + warp*16 + r;
    if (gr < Nn) {
        float* p = &Cst[warp][r][cc];
        __half2 h[8];
        #pragma unroll
        for (int q = 0; q < 8; q++) h[q] = __floats2half2_rn(p[2*q], p[2*q+1]);
        *reinterpret_cast<uint4*>(&g_hs2h[gr*HID + cc])     = *reinterpret_cast<uint4*>(h);
        *reinterpret_cast<uint4*>(&g_hs2h[gr*HID + cc + 8]) = *reinterpret_cast<uint4*>(h + 4);
    }
}

// ---------------- layer-2 aggregate with inline softmax: warp per dst node ----------------
__global__ void agg2_fused(float* __restrict__ dout, const float* __restrict__ b2) {
    int node = (blockIdx.x * blockDim.x + threadIdx.x) >> 5;
    if (node >= Nn) return;
    int lane = threadIdx.x & 31;
    float adv = g_ad2[node];
    int start = g_rowptr[node], end = g_rowptr[node + 1];
    float acc = 0.f, wsum = 0.f;
    int j = start;
    for (; j + 4 <= end; j += 4) {
        int s0 = g_esrc[j], s1 = g_esrc[j+1], s2 = g_esrc[j+2], s3 = g_esrc[j+3];
        float w0 = __expf(leaky(g_as2[s0] + adv));
        float w1 = __expf(leaky(g_as2[s1] + adv));
        float w2 = __expf(leaky(g_as2[s2] + adv));
        float w3 = __expf(leaky(g_as2[s3] + adv));
        float v0 = __half2float(g_hs2h[s0*HID + lane]);
        float v1 = __half2float(g_hs2h[s1*HID + lane]);
        float v2 = __half2float(g_hs2h[s2*HID + lane]);
        float v3 = __half2float(g_hs2h[s3*HID + lane]);
        wsum += (w0 + w1) + (w2 + w3);
        acc += w0*v0 + w1*v1 + w2*v2 + w3*v3;
    }
    for (; j < end; j++) {
        int s0 = g_esrc[j];
        float w0 = __expf(leaky(g_as2[s0] + adv));
        wsum += w0;
        acc += w0 * __half2float(g_hs2h[s0*HID + lane]);
    }
    dout[node*HID + lane] = acc / (wsum + 1e-16f) + b2[lane];
}

// ---------------- launch (round-13 structure) ----------------
extern "C" void kernel_launch(void* const* d_in, const int* in_sizes, int n_in,
                              void* d_out, int out_size) {
    const float* x   = (const float*)d_in[0];
    const int*   ei  = (const int*)d_in[1];
    const float* W1s = (const float*)d_in[2];
    const float* W1d = (const float*)d_in[3];
    const float* a1s = (const float*)d_in[4];
    const float* a1d = (const float*)d_in[5];
    const float* b1  = (const float*)d_in[6];
    const float* W2s = (const float*)d_in[7];
    const float* W2d = (const float*)d_in[8];
    const float* a2s = (const float*)d_in[9];
    const float* a2d = (const float*)d_in[10];
    const float* b2  = (const float*)d_in[11];
    float* dout = (float*)d_out;

    int eb   = (Ee + 255)/256;
    int nb32 = (Nn*32 + 255)/256;

    cudaStream_t sB, sC;
    cudaEvent_t e0, e1, e2, e3;
    cudaStreamCreateWithFlags(&sB, cudaStreamNonBlocking);
    cudaStreamCreateWithFlags(&sC, cudaStreamNonBlocking);
    cudaEventCreateWithFlags(&e0, cudaEventDisableTiming);
    cudaEventCreateWithFlags(&e1, cudaEventDisableTiming);
    cudaEventCreateWithFlags(&e2, cudaEventDisableTiming);
    cudaEventCreateWithFlags(&e3, cudaEventDisableTiming);

    cudaEventRecord(e0, 0);
    cudaStreamWaitEvent(sB, e0, 0);
    cudaStreamWaitEvent(sC, e0, 0);

    // stream 0: CSR build
    convert_hist<<<eb, 256>>>(ei);
    scan_blocks<<<SB, 1024>>>();
    cudaEventRecord(e3, 0);                 // g_deg fully consumed
    scan_add<<<(Nn + 255)/256, 256>>>();
    fill_kernel<<<eb, 256>>>(ei);

    // stream B: layer-1 tensor-core GEMM, then re-zero g_deg off the critical path
    dim3 g1(F1/64, (Nn + 127)/128);
    gemm1_wmma<<<g1, 256, 0, sB>>>(x, W1s);
    cudaStreamWaitEvent(sB, e3, 0);
    zero_deg<<<(Nn + 255)/256, 256, 0, sB>>>();
    cudaEventRecord(e1, sB);

    // stream C: attention weight reduction + layer-1 alphas
    reduceW_kernel<<<6, 256, 0, sC>>>(W1s, W1d, a1s, a1d, W2s, W2d, a2s, a2d);
    alpha1_kernel<<<nb32, 256, 0, sC>>>(x);
    cudaEventRecord(e2, sC);

    // join
    cudaStreamWaitEvent(0, e1, 0);
    cudaStreamWaitEvent(0, e2, 0);

    agg1_fused<<<nb32, 256>>>(b1);          // also produces layer-2 alphas
    gemm2_wmma<<<(NPAD + 127)/128, 256>>>(W2s);
    agg2_fused<<<nb32, 256>>>(dout, b2);

    cudaStreamDestroy(sB);
    cudaStreamDestroy(sC);
    cudaEventDestroy(e0);
    cudaEventDestroy(e1);
    cudaEventDestroy(e2);
    cudaEventDestroy(e3);
}

// round 16
// speedup vs baseline: 1.5231x; 1.5231x over previous
#include <cuda_runtime.h>
#include <cuda_fp16.h>
#include <math_constants.h>
#include <mma.h>

using namespace nvcuda;

#define Nn 50000
#define Ee 800000
#define DIN 128
#define HID 32
#define HEADS 8
#define F1 (HEADS*HID)   // 256
#define NPAD 50048       // Nn rounded up to 128 (WMMA M-tile)
#define SB 49            // scan blocks = ceil(Nn/1024)

// ---------------- scratch (static device globals; no allocation) ----------------
// g_deg relies on zero-init for the first call; re-zeroed (zero_deg) each run.
__device__ __half g_hs1h[NPAD*F1];   // layer1 source features, fp16 [N,256]
__device__ __half g_aggh[NPAD*F1];   // layer1 output h, fp16 [N,256]
__device__ __half g_hs2h[NPAD*HID];  // layer2 source features, fp16 [N,32]
__device__ float g_as1[Nn*HEADS], g_ad1[Nn*HEADS];
__device__ float g_as2[Nn], g_ad2[Nn];
__device__ float g_Wsr1[HEADS*DIN], g_Wdr1[HEADS*DIN];   // [h][k] layout
__device__ float g_Wsr2[F1], g_Wdr2[F1];
__device__ int   g_deg[Nn];
__device__ int   g_rowptr[Nn + 1];
__device__ int   g_cursor[Nn];
__device__ int   g_esrc[Ee];
__device__ int   g_bsum[64];

__device__ __forceinline__ float leaky(float v) { return v > 0.f ? v : 0.2f * v; }

__device__ __forceinline__ uint2 pack4h(float4 v) {
    __half2 h0 = __floats2half2_rn(v.x, v.y);
    __half2 h1 = __floats2half2_rn(v.z, v.w);
    uint2 r;
    r.x = *reinterpret_cast<unsigned*>(&h0);
    r.y = *reinterpret_cast<unsigned*>(&h1);
    return r;
}

__device__ __forceinline__ bool detect_i64(const int* __restrict__ raw) {
    bool is_i64 = true;
    #pragma unroll
    for (int i = 0; i < 16; i++)
        if (raw[2*i + 1] != 0) is_i64 = false;
    return is_i64;
}

// ---------------- histogram of dst straight from raw edge buffer ----------------
__global__ void convert_hist(const int* __restrict__ raw) {
    bool is_i64 = detect_i64(raw);
    int e = blockIdx.x * blockDim.x + threadIdx.x;
    if (e >= Ee) return;
    int d = is_i64 ? raw[2*(Ee + e)] : raw[Ee + e];
    atomicAdd(&g_deg[d], 1);
}

// ---------------- per-1024-chunk scan ----------------
__global__ void scan_blocks() {
    __shared__ int sm[1024];
    int gid = blockIdx.x * 1024 + threadIdx.x;
    int v = (gid < Nn) ? g_deg[gid] : 0;
    sm[threadIdx.x] = v;
    __syncthreads();
    for (int off = 1; off < 1024; off <<= 1) {
        int t = (threadIdx.x >= off) ? sm[threadIdx.x - off] : 0;
        __syncthreads();
        sm[threadIdx.x] += t;
        __syncthreads();
    }
    if (gid < Nn) g_rowptr[gid] = sm[threadIdx.x] - v;
    if (threadIdx.x == 1023) g_bsum[blockIdx.x] = sm[1023];
}

__global__ void zero_deg() {
    int i = blockIdx.x * blockDim.x + threadIdx.x;
    if (i < Nn) g_deg[i] = 0;
}

// ---------------- add chunk offsets (scans the 49 block sums locally) ----------------
__global__ void scan_add() {
    __shared__ int pref[64];
    int t = threadIdx.x;
    if (t < 64) pref[t] = (t < SB) ? g_bsum[t] : 0;
    __syncthreads();
    if (t == 0) {
        int run = 0;
        #pragma unroll
        for (int i = 0; i < 64; i++) { int v = pref[i]; pref[i] = run; run += v; }
    }
    __syncthreads();
    int gid = blockIdx.x * blockDim.x + t;
    if (gid < Nn) {
        int r = g_rowptr[gid] + pref[gid >> 10];
        g_rowptr[gid] = r;
        g_cursor[gid] = r;
    }
    if (gid == 0) g_rowptr[Nn] = Ee;
}

// ---------------- CSR fill ----------------
__global__ void fill_kernel(const int* __restrict__ raw) {
    bool is_i64 = detect_i64(raw);
    int e = blockIdx.x * blockDim.x + threadIdx.x;
    if (e >= Ee) return;
    int s, d;
    if (is_i64) { s = raw[2*e]; d = raw[2*(Ee + e)]; }
    else        { s = raw[e];   d = raw[Ee + e]; }
    int pos = atomicAdd(&g_cursor[d], 1);
    g_esrc[pos] = s;
}

// ---------------- reduce attention weight vectors ----------------
__global__ void reduceW_kernel(const float* __restrict__ W1s, const float* __restrict__ W1d,
                               const float* __restrict__ a1s, const float* __restrict__ a1d,
                               const float* __restrict__ W2s, const float* __restrict__ W2d,
                               const float* __restrict__ a2s, const float* __restrict__ a2d) {
    int idx = blockIdx.x * blockDim.x + threadIdx.x;
    if (idx < HEADS*DIN) {
        int h = idx >> 7, k = idx & 127;
        float s = 0.f, d = 0.f;
        #pragma unroll
        for (int c = 0; c < HID; c++) {
            s += W1s[k*F1 + h*HID + c] * a1s[h*HID + c];
            d += W1d[k*F1 + h*HID + c] * a1d[h*HID + c];
        }
        g_Wsr1[h*DIN + k] = s;
        g_Wdr1[h*DIN + k] = d;
    } else if (idx < HEADS*DIN + F1) {
        int k = idx - HEADS*DIN;
        float s = 0.f, d = 0.f;
        #pragma unroll
        for (int c = 0; c < HID; c++) {
            s += W2s[k*HID + c] * a2s[c];
            d += W2d[k*HID + c] * a2d[c];
        }
        g_Wsr2[k] = s;
        g_Wdr2[k] = d;
    }
}

// ---------------- layer-1 GEMM via WMMA, K-tile 32, inline fp32->fp16 staging ----------------
__global__ void gemm1_wmma(const float* __restrict__ A, const float* __restrict__ B) {
    __shared__ __half As[128][40];
    __shared__ __half Bs[32][72];
    __shared__ float  Cst[8][16][20];
    int tid = threadIdx.x;
    int warp = tid >> 5, lane = tid & 31;
    int bm = blockIdx.y * 128, bn = blockIdx.x * 64;
    int wm = warp >> 1, wn = warp & 1;

    wmma::fragment<wmma::accumulator, 16, 16, 16, float> c[2][2];
    #pragma unroll
    for (int i = 0; i < 2; i++)
        #pragma unroll
        for (int j = 0; j < 2; j++)
            wmma::fill_fragment(c[i][j], 0.f);

    for (int k0 = 0; k0 < DIN; k0 += 32) {
        {
            int ar = tid >> 1, ac = (tid & 1) * 16;
            int gr = bm + ar;
            #pragma unroll
            for (int q = 0; q < 4; q++) {
                float4 v = make_float4(0.f, 0.f, 0.f, 0.f);
                if (gr < Nn) v = *reinterpret_cast<const float4*>(&A[gr*DIN + k0 + ac + q*4]);
                *reinterpret_cast<uint2*>(&As[ar][ac + q*4]) = pack4h(v);
            }
        }
        {
            int br = tid >> 3, bc = (tid & 7) * 8;
            #pragma unroll
            for (int q = 0; q < 2; q++) {
                float4 v = *reinterpret_cast<const float4*>(&B[(k0 + br)*F1 + bn + bc + q*4]);
                *reinterpret_cast<uint2*>(&Bs[br][bc + q*4]) = pack4h(v);
            }
        }
        __syncthreads();
        #pragma unroll
        for (int ks = 0; ks < 32; ks += 16) {
            wmma::fragment<wmma::matrix_a, 16, 16, 16, __half, wmma::row_major> a[2];
            wmma::fragment<wmma::matrix_b, 16, 16, 16, __half, wmma::row_major> b[2];
            #pragma unroll
            for (int i = 0; i < 2; i++)
                wmma::load_matrix_sync(a[i], &As[wm*32 + i*16][ks], 40);
            #pragma unroll
            for (int j = 0; j < 2; j++)
                wmma::load_matrix_sync(b[j], &Bs[ks][wn*32 + j*16], 72);
            #pragma unroll
            for (int i = 0; i < 2; i++)
                #pragma unroll
                for (int j = 0; j < 2; j++)
                    wmma::mma_sync(c[i][j], a[i], b[j], c[i][j]);
        }
        __syncthreads();
    }

    #pragma unroll
    for (int i = 0; i < 2; i++)
        #pragma unroll
        for (int j = 0; j < 2; j++) {
            wmma::store_matrix_sync(&Cst[warp][0][0], c[i][j], 20, wmma::mem_row_major);
            __syncwarp();
            int r = lane >> 1, cc = (lane & 1) * 8;
            int gr = bm + wm*32 + i*16 + r;
            if (gr < Nn) {
                float* p = &Cst[warp][r][cc];
                __half2 h[4];
                h[0] = __floats2half2_rn(p[0], p[1]);
                h[1] = __floats2half2_rn(p[2], p[3]);
                h[2] = __floats2half2_rn(p[4], p[5]);
                h[3] = __floats2half2_rn(p[6], p[7]);
                *reinterpret_cast<uint4*>(&g_hs1h[gr*F1 + bn + wn*32 + j*16 + cc]) =
                    *reinterpret_cast<uint4*>(h);
            }
            __syncwarp();
        }
}

// ---------------- layer-1 alphas: warp per node (fp32 x) ----------------
__global__ void alpha1_kernel(const float* __restrict__ x) {
    int warp = (blockIdx.x * blockDim.x + threadIdx.x) >> 5;
    if (warp >= Nn) return;
    int lane = threadIdx.x & 31;
    float xv0 = x[warp*DIN + lane];
    float xv1 = x[warp*DIN + 32 + lane];
    float xv2 = x[warp*DIN + 64 + lane];
    float xv3 = x[warp*DIN + 96 + lane];
    #pragma unroll
    for (int h = 0; h < HEADS; h++) {
        const float* ws = &g_Wsr1[h*DIN];
        const float* wd = &g_Wdr1[h*DIN];
        float s = xv0*ws[lane] + xv1*ws[32+lane] + xv2*ws[64+lane] + xv3*ws[96+lane];
        float d = xv0*wd[lane] + xv1*wd[32+lane] + xv2*wd[64+lane] + xv3*wd[96+lane];
        #pragma unroll
        for (int off = 16; off; off >>= 1) {
            s += __shfl_down_sync(0xffffffffu, s, off);
            d += __shfl_down_sync(0xffffffffu, d, off);
        }
        if (lane == 0) { g_as1[warp*HEADS + h] = s; g_ad1[warp*HEADS + h] = d; }
    }
}

// ---------------- layer-1 aggregate + inline softmax + fused layer-2 alphas ----------------
__device__ __forceinline__ void fma8h(float* acc, float w, uint4 u) {
    __half2 h0 = *reinterpret_cast<__half2*>(&u.x);
    __half2 h1 = *reinterpret_cast<__half2*>(&u.y);
    __half2 h2 = *reinterpret_cast<__half2*>(&u.z);
    __half2 h3 = *reinterpret_cast<__half2*>(&u.w);
    float2 f0 = __half22float2(h0);
    float2 f1 = __half22float2(h1);
    float2 f2 = __half22float2(h2);
    float2 f3 = __half22float2(h3);
    acc[0] += w*f0.x; acc[1] += w*f0.y;
    acc[2] += w*f1.x; acc[3] += w*f1.y;
    acc[4] += w*f2.x; acc[5] += w*f2.y;
    acc[6] += w*f3.x; acc[7] += w*f3.y;
}

__global__ void agg1_fused(const float* __restrict__ b1) {
    int node = (blockIdx.x * blockDim.x + threadIdx.x) >> 5;
    if (node >= Nn) return;
    int lane = threadIdx.x & 31;
    int wh = lane >> 2;
    float adv = g_ad1[node*HEADS + wh];
    int start = g_rowptr[node], end = g_rowptr[node + 1];

    float acc[8] = {};
    float wsum = 0.f;
    int j = start;
    for (; j + 2 <= end; j += 2) {
        int s0 = g_esrc[j], s1 = g_esrc[j+1];
        float w0 = __expf(leaky(g_as1[s0*HEADS + wh] + adv));
        float w1 = __expf(leaky(g_as1[s1*HEADS + wh] + adv));
        uint4 u0 = *reinterpret_cast<const uint4*>(&g_hs1h[s0*F1 + lane*8]);
        uint4 u1 = *reinterpret_cast<const uint4*>(&g_hs1h[s1*F1 + lane*8]);
        wsum += w0 + w1;
        fma8h(acc, w0, u0);
        fma8h(acc, w1, u1);
    }
    if (j < end) {
        int s0 = g_esrc[j];
        float w0 = __expf(leaky(g_as1[s0*HEADS + wh] + adv));
        uint4 u0 = *reinterpret_cast<const uint4*>(&g_hs1h[s0*F1 + lane*8]);
        wsum += w0;
        fma8h(acc, w0, u0);
    }
    float inv = 1.f / (wsum + 1e-16f);
    float4 bb0 = *reinterpret_cast<const float4*>(&b1[lane*8]);
    float4 bb1 = *reinterpret_cast<const float4*>(&b1[lane*8 + 4]);
    float o[8];
    o[0] = fmaxf(acc[0]*inv + bb0.x, 0.f); o[1] = fmaxf(acc[1]*inv + bb0.y, 0.f);
    o[2] = fmaxf(acc[2]*inv + bb0.z, 0.f); o[3] = fmaxf(acc[3]*inv + bb0.w, 0.f);
    o[4] = fmaxf(acc[4]*inv + bb1.x, 0.f); o[5] = fmaxf(acc[5]*inv + bb1.y, 0.f);
    o[6] = fmaxf(acc[6]*inv + bb1.z, 0.f); o[7] = fmaxf(acc[7]*inv + bb1.w, 0.f);
    uint2 p0 = pack4h(make_float4(o[0], o[1], o[2], o[3]));
    uint2 p1 = pack4h(make_float4(o[4], o[5], o[6], o[7]));
    *reinterpret_cast<uint4*>(&g_aggh[node*F1 + lane*8]) = make_uint4(p0.x, p0.y, p1.x, p1.y);

    // fused layer-2 alphas (fp32 h, pre-quantization)
    float4 ws0 = *reinterpret_cast<const float4*>(&g_Wsr2[lane*8]);
    float4 ws1 = *reinterpret_cast<const float4*>(&g_Wsr2[lane*8 + 4]);
    float4 wd0 = *reinterpret_cast<const float4*>(&g_Wdr2[lane*8]);
    float4 wd1 = *reinterpret_cast<const float4*>(&g_Wdr2[lane*8 + 4]);
    float s = o[0]*ws0.x + o[1]*ws0.y + o[2]*ws0.z + o[3]*ws0.w
            + o[4]*ws1.x + o[5]*ws1.y + o[6]*ws1.z + o[7]*ws1.w;
    float d = o[0]*wd0.x + o[1]*wd0.y + o[2]*wd0.z + o[3]*wd0.w
            + o[4]*wd1.x + o[5]*wd1.y + o[6]*wd1.z + o[7]*wd1.w;
    #pragma unroll
    for (int off = 16; off; off >>= 1) {
        s += __shfl_down_sync(0xffffffffu, s, off);
        d += __shfl_down_sync(0xffffffffu, d, off);
    }
    if (lane == 0) { g_as2[node] = s; g_ad2[node] = d; }
}

// ---------------- layer-2 GEMM via WMMA: hs2 = h[N,256] @ W2_src[256,32] ----------------
__global__ void gemm2_wmma(const float* __restrict__ W2s) {
    __shared__ __half Bs[256][40];
    __shared__ float  Cst[8][16][36];
    int tid = threadIdx.x;
    int warp = tid >> 5, lane = tid & 31;
    int bm = blockIdx.x * 128;

    {
        int row = tid;
        #pragma unroll
        for (int q = 0; q < 8; q++) {
            float4 v = *reinterpret_cast<const float4*>(&W2s[row*HID + q*4]);
            *reinterpret_cast<uint2*>(&Bs[row][q*4]) = pack4h(v);
        }
    }
    __syncthreads();

    wmma::fragment<wmma::accumulator, 16, 16, 16, float> c[2];
    wmma::fill_fragment(c[0], 0.f);
    wmma::fill_fragment(c[1], 0.f);

    const __half* arow = &g_aggh[(bm + warp*16)*F1];
    #pragma unroll
    for (int k0 = 0; k0 < F1; k0 += 16) {
        wmma::fragment<wmma::matrix_a, 16, 16, 16, __half, wmma::row_major> a;
        wmma::load_matrix_sync(a, arow + k0, F1);
        wmma::fragment<wmma::matrix_b, 16, 16, 16, __half, wmma::row_major> b0, b1;
        wmma::load_matrix_sync(b0, &Bs[k0][0], 40);
        wmma::load_matrix_sync(b1, &Bs[k0][16], 40);
        wmma::mma_sync(c[0], a, b0, c[0]);
        wmma::mma_sync(c[1], a, b1, c[1]);
    }

    wmma::store_matrix_sync(&Cst[warp][0][0],  c[0], 36, wmma::mem_row_major);
    wmma::store_matrix_sync(&Cst[warp][0][16], c[1], 36, wmma::mem_row_major);
    __syncwarp();
    int r = lane >> 1, cc = (lane & 1) * 16;
    int gr = bm + warp*16 + r;
    if (gr < Nn) {
        float* p = &Cst[warp][r][cc];
        __half2 h[8];
        #pragma unroll
        for (int q = 0; q < 8; q++) h[q] = __floats2half2_rn(p[2*q], p[2*q+1]);
        *reinterpret_cast<uint4*>(&g_hs2h[gr*HID + cc])     = *reinterpret_cast<uint4*>(h);
        *reinterpret_cast<uint4*>(&g_hs2h[gr*HID + cc + 8]) = *reinterpret_cast<uint4*>(h + 4);
    }
}

// ---------------- layer-2 aggregate with inline softmax: warp per dst node ----------------
__global__ void agg2_fused(float* __restrict__ dout, const float* __restrict__ b2) {
    int node = (blockIdx.x * blockDim.x + threadIdx.x) >> 5;
    if (node >= Nn) return;
    int lane = threadIdx.x & 31;
    float adv = g_ad2[node];
    int start = g_rowptr[node], end = g_rowptr[node + 1];
    float acc = 0.f, wsum = 0.f;
    int j = start;
    for (; j + 2 <= end; j += 2) {
        int s0 = g_esrc[j], s1 = g_esrc[j+1];
        float w0 = __expf(leaky(g_as2[s0] + adv));
        float w1 = __expf(leaky(g_as2[s1] + adv));
        float v0 = __half2float(g_hs2h[s0*HID + lane]);
        float v1 = __half2float(g_hs2h[s1*HID + lane]);
        wsum += w0 + w1;
        acc += w0*v0 + w1*v1;
    }
    if (j < end) {
        int s0 = g_esrc[j];
        float w0 = __expf(leaky(g_as2[s0] + adv));
        wsum += w0;
        acc += w0 * __half2float(g_hs2h[s0*HID + lane]);
    }
    dout[node*HID + lane] = acc / (wsum + 1e-16f) + b2[lane];
}

// ---------------- launch (round-13 structure, exact) ----------------
extern "C" void kernel_launch(void* const* d_in, const int* in_sizes, int n_in,
                              void* d_out, int out_size) {
    const float* x   = (const float*)d_in[0];
    const int*   ei  = (const int*)d_in[1];
    const float* W1s = (const float*)d_in[2];
    const float* W1d = (const float*)d_in[3];
    const float* a1s = (const float*)d_in[4];
    const float* a1d = (const float*)d_in[5];
    const float* b1  = (const float*)d_in[6];
    const float* W2s = (const float*)d_in[7];
    const float* W2d = (const float*)d_in[8];
    const float* a2s = (const float*)d_in[9];
    const float* a2d = (const float*)d_in[10];
    const float* b2  = (const float*)d_in[11];
    float* dout = (float*)d_out;

    int eb   = (Ee + 255)/256;
    int nb32 = (Nn*32 + 255)/256;

    cudaStream_t sB, sC;
    cudaEvent_t e0, e1, e2, e3;
    cudaStreamCreateWithFlags(&sB, cudaStreamNonBlocking);
    cudaStreamCreateWithFlags(&sC, cudaStreamNonBlocking);
    cudaEventCreateWithFlags(&e0, cudaEventDisableTiming);
    cudaEventCreateWithFlags(&e1, cudaEventDisableTiming);
    cudaEventCreateWithFlags(&e2, cudaEventDisableTiming);
    cudaEventCreateWithFlags(&e3, cudaEventDisableTiming);

    cudaEventRecord(e0, 0);
    cudaStreamWaitEvent(sB, e0, 0);
    cudaStreamWaitEvent(sC, e0, 0);

    // stream 0: CSR build
    convert_hist<<<eb, 256>>>(ei);
    scan_blocks<<<SB, 1024>>>();
    cudaEventRecord(e3, 0);                 // g_deg fully consumed
    scan_add<<<(Nn + 255)/256, 256>>>();
    fill_kernel<<<eb, 256>>>(ei);

    // stream B: layer-1 tensor-core GEMM, then re-zero g_deg off the critical path
    dim3 g1(F1/64, (Nn + 127)/128);
    gemm1_wmma<<<g1, 256, 0, sB>>>(x, W1s);
    cudaStreamWaitEvent(sB, e3, 0);
    zero_deg<<<(Nn + 255)/256, 256, 0, sB>>>();
    cudaEventRecord(e1, sB);

    // stream C: attention weight reduction + layer-1 alphas
    reduceW_kernel<<<6, 256, 0, sC>>>(W1s, W1d, a1s, a1d, W2s, W2d, a2s, a2d);
    alpha1_kernel<<<nb32, 256, 0, sC>>>(x);
    cudaEventRecord(e2, sC);

    // join
    cudaStreamWaitEvent(0, e1, 0);
    cudaStreamWaitEvent(0, e2, 0);

    agg1_fused<<<nb32, 256>>>(b1);          // also produces layer-2 alphas
    gemm2_wmma<<<(NPAD + 127)/128, 256>>>(W2s);
    agg2_fused<<<nb32, 256>>>(dout, b2);

    cudaStreamDestroy(sB);
    cudaStreamDestroy(sC);
    cudaEventDestroy(e0);
    cudaEventDestroy(e1);
    cudaEventDestroy(e2);
    cudaEventDestroy(e3);
}